// round 12
// baseline (speedup 1.0000x reference)
#include <cuda_runtime.h>
#include <math.h>
#include <stdint.h>

// Problem constants
#define BQ    512
#define EDIM  512
#define CDIM  70722
#define TWC   (2*CDIM)
#define EPSF  0.001f
#define HF    0.333f
#define SF    64.0f
#define MMARG 0.4f
#define TALPHA 1.0f

// GEMM tile config
#define BM 128
#define BN 128
#define BK 32
#define NCH (EDIM/BK)               // 16 chunks
#define RS 40                       // smem row stride in halves (80B)
#define TILE_H   (BM*RS)
#define TILE_B   (TILE_H*2)         // 10240 bytes per tile
#define BUF_B    (2*TILE_B)         // Ah,Bh = 20480 bytes per stage
#define SSQP_OFF (2*BUF_B)          // 40960
#define SINV_OFF (SSQP_OFF + 512*4) // 43008
#define SMEM_SZ  (SINV_OFF + BN*4)  // 43520

// Scratch
__device__ float d_gang[BQ];
__device__ float d_gadd[BQ];

// ============================ helpers ======================================
__device__ __forceinline__ uint32_t smem_u32(const void* p) {
    uint32_t a;
    asm("{ .reg .u64 t; cvta.to.shared.u64 t, %1; cvt.u32.u64 %0, t; }" : "=r"(a) : "l"(p));
    return a;
}
__device__ __forceinline__ void ldsm4(uint32_t* r, uint32_t addr) {
    asm volatile("ldmatrix.sync.aligned.m8n8.x4.shared.b16 {%0,%1,%2,%3}, [%4];"
        : "=r"(r[0]), "=r"(r[1]), "=r"(r[2]), "=r"(r[3]) : "r"(addr));
}
__device__ __forceinline__ void mma_f16(float* c, const uint32_t* a, const uint32_t* b) {
    asm volatile(
        "mma.sync.aligned.m16n8k16.row.col.f32.f16.f16.f32 "
        "{%0,%1,%2,%3}, {%4,%5,%6,%7}, {%8,%9}, {%0,%1,%2,%3};"
        : "+f"(c[0]), "+f"(c[1]), "+f"(c[2]), "+f"(c[3])
        : "r"(a[0]), "r"(a[1]), "r"(a[2]), "r"(a[3]), "r"(b[0]), "r"(b[1]));
}
__device__ __forceinline__ uint32_t pack_f16(float x0, float x1) {
    uint32_t p;
    asm("cvt.rn.f16x2.f32 %0, %1, %2;" : "=r"(p) : "f"(x1), "f"(x0));
    return p;
}

// ---------------------------------------------------------------------------
// K3: batch statistics + cw_margin output
// ---------------------------------------------------------------------------
__global__ void stats_kernel(const float* __restrict__ norms,
                             const int*   __restrict__ label,
                             float* __restrict__ out) {
    __shared__ float sn[BQ];
    __shared__ int   lab[BQ];
    __shared__ float red[BQ];
    int t = threadIdx.x;
    float x = fminf(fmaxf(norms[t], 0.001f), 100.0f);
    sn[t] = x; lab[t] = label[t]; red[t] = x;
    __syncthreads();
    for (int o = 256; o > 0; o >>= 1) { if (t < o) red[t] += red[t+o]; __syncthreads(); }
    float mean = red[0] * (1.0f / BQ);
    __syncthreads();
    float d = x - mean;
    red[t] = d * d;
    __syncthreads();
    for (int o = 256; o > 0; o >>= 1) { if (t < o) red[t] += red[t+o]; __syncthreads(); }
    float stdv = sqrtf(red[0] / (float)(BQ - 1));
    float batch_mean = mean * TALPHA + (1.0f - TALPHA) * 20.0f;
    float batch_std  = stdv * TALPHA + (1.0f - TALPHA) * 10.0f;
    int ml = lab[t];
    float s = 0.f; int cnt = 0;
    for (int j = 0; j < BQ; ++j) if (lab[j] == ml) { s += sn[j]; cnt++; }
    float cwm = (s / (float)cnt) * TALPHA + (1.0f - TALPHA) * 20.0f;
    float inv = 1.0f / (batch_std + EPSF);
    float ms = fminf(fmaxf((x - batch_mean) * inv * HF, -1.0f), 1.0f);
    d_gang[t] = -MMARG * ms;
    d_gadd[t] =  MMARG + MMARG * ms;
    out[(size_t)2 * BQ * CDIM + t] = fminf(fmaxf((x - cwm) * inv, -1.0f), 1.0f) * HF;
}

// ---------------------------------------------------------------------------
// K4: fp16 mma.sync GEMM, 512 threads, double-buffered, distance-2 prefetch,
// ONE barrier per chunk. 16 warps (4m x 4n), warp tile 32x32.
// ---------------------------------------------------------------------------
__global__ void __launch_bounds__(512, 1)
gemm_kernel(const float* __restrict__ A,       // emb [512,512]
            const float* __restrict__ Kn,      // kernel t=0 plane (stride TWC)
            float* __restrict__ out) {
    extern __shared__ char smem[];
    const uint32_t sb = smem_u32(smem);
    float* ssqp = (float*)(smem + SSQP_OFF);
    float* sinv = (float*)(smem + SINV_OFF);

    const int t = threadIdx.x;
    const int lane = t & 31;
    const int wid = t >> 5;
    const int mbase = blockIdx.x * BM;
    const int cbase = blockIdx.y * BN;
    const int wm = (wid >> 2) * 32;
    const int wn = (wid & 3) * 32;

    float acc[2][4][4];
    #pragma unroll
    for (int i = 0; i < 2; ++i)
        #pragma unroll
        for (int j = 0; j < 4; ++j)
            #pragma unroll
            for (int r = 0; r < 4; ++r) acc[i][j][r] = 0.f;

    // B-load mapping: 4 threads per column, 8 k's each
    const int bn  = t & 127;
    const int bkh = (t >> 7) * 8;
    const int bc  = cbase + bn;
    const bool bvalid = bc < CDIM;
    float ssq = 0.f;

    // A-load mapping: 2 float4 per thread
    const int a_m0 = t >> 3, a_q = t & 7;
    const int a_m1 = a_m0 + 64;

    // ldmatrix lane addressing
    const int a_row  = wm + (lane & 15);
    const int a_coff = (lane >> 4) * 8;
    const int b_n    = wn + ((lane >> 4) << 3) + (lane & 7);
    const int b_koff = ((lane >> 3) & 1) * 8;

    // distance-2 prefetch registers: slot s holds chunk data for the next
    // chunk with (ch & 1) == s that hasn't been converted yet.
    float4 apre[2][2];
    float  bpre[2][8];
    #pragma unroll
    for (int s = 0; s < 2; ++s) {
        const int kb = s * BK;
        apre[s][0] = *(const float4*)&A[(size_t)(mbase + a_m0) * EDIM + kb + a_q * 4];
        apre[s][1] = *(const float4*)&A[(size_t)(mbase + a_m1) * EDIM + kb + a_q * 4];
        #pragma unroll
        for (int j = 0; j < 8; ++j)
            bpre[s][j] = bvalid ? Kn[(size_t)(kb + bkh + j) * TWC + bc] : 0.f;
    }

    for (int ch = 0; ch < NCH; ++ch) {
        const int cur = ch & 1;
        const uint32_t cb = sb + cur * BUF_B;

        // ---- convert prefetched chunk into its buffer ----
        {
            uint16_t* Ah = (uint16_t*)(smem + cur * BUF_B);
            uint16_t* Bh = (uint16_t*)(smem + cur * BUF_B + TILE_B);
            float4 v0 = apre[cur][0], v1 = apre[cur][1];
            *(uint2*)&Ah[a_m0 * RS + a_q * 4] =
                make_uint2(pack_f16(v0.x, v0.y), pack_f16(v0.z, v0.w));
            *(uint2*)&Ah[a_m1 * RS + a_q * 4] =
                make_uint2(pack_f16(v1.x, v1.y), pack_f16(v1.z, v1.w));
            #pragma unroll
            for (int j = 0; j < 8; j += 2) {
                float b0 = bpre[cur][j], b1 = bpre[cur][j+1];
                ssq += b0 * b0 + b1 * b1;
                *(uint32_t*)&Bh[bn * RS + bkh + j] = pack_f16(b0, b1);
            }
        }
        __syncthreads();   // single barrier per chunk (see safety proof in header)

        // ---- issue loads for chunk ch+2 into the slot just consumed ----
        if (ch + 2 < NCH) {
            const int kb = (ch + 2) * BK;
            apre[cur][0] = *(const float4*)&A[(size_t)(mbase + a_m0) * EDIM + kb + a_q * 4];
            apre[cur][1] = *(const float4*)&A[(size_t)(mbase + a_m1) * EDIM + kb + a_q * 4];
            #pragma unroll
            for (int j = 0; j < 8; ++j)
                bpre[cur][j] = bvalid ? Kn[(size_t)(kb + bkh + j) * TWC + bc] : 0.f;
        }

        // ---- math on current buffer ----
        const uint32_t aH = cb;
        const uint32_t bH = cb + TILE_B;
        #pragma unroll
        for (int kf = 0; kf < 2; ++kf) {
            const int kc = kf * 16;
            uint32_t ah[2][4], bhf[4][2];
            #pragma unroll
            for (int mf = 0; mf < 2; ++mf) {
                uint32_t ad = ((uint32_t)((a_row + mf * 16) * RS + kc + a_coff)) * 2;
                ldsm4(ah[mf], aH + ad);
            }
            {
                uint32_t bd0 = ((uint32_t)(b_n * RS + kc + b_koff)) * 2;
                uint32_t bd1 = ((uint32_t)((b_n + 16) * RS + kc + b_koff)) * 2;
                uint32_t r[4];
                ldsm4(r, bH + bd0);
                bhf[0][0]=r[0]; bhf[0][1]=r[1]; bhf[1][0]=r[2]; bhf[1][1]=r[3];
                ldsm4(r, bH + bd1);
                bhf[2][0]=r[0]; bhf[2][1]=r[1]; bhf[3][0]=r[2]; bhf[3][1]=r[3];
            }
            #pragma unroll
            for (int mf = 0; mf < 2; ++mf)
                #pragma unroll
                for (int nf = 0; nf < 4; ++nf)
                    mma_f16(acc[mf][nf], ah[mf], bhf[nf]);
        }
        // NOTE: no end-of-chunk barrier. Safety: conv(ch+2) writes buf[cur]
        // only after the sync inside iteration ch+1, which every thread
        // reaches only after finishing math(ch) on buf[cur].
    }

    __syncthreads();
    // ---- column inverse norms (fp32-exact) ----
    ssqp[t] = ssq;
    __syncthreads();
    if (t < 128)
        sinv[t] = rsqrtf(ssqp[t] + ssqp[t + 128] + ssqp[t + 256] + ssqp[t + 384]);
    __syncthreads();

    // ---- epilogue: clip*scale, dual-plane float2 stores ----
    const float lo = -1.0f + EPSF, hi = 1.0f - EPSF;
    float inv[4][2];
    #pragma unroll
    for (int nf = 0; nf < 4; ++nf) {
        int c0 = wn + nf * 8 + (lane & 3) * 2;
        inv[nf][0] = sinv[c0];
        inv[nf][1] = sinv[c0 + 1];
    }
    #pragma unroll
    for (int mf = 0; mf < 2; ++mf) {
        int row0 = mbase + wm + mf * 16 + (lane >> 2);
        #pragma unroll
        for (int nf = 0; nf < 4; ++nf) {
            int col = cbase + wn + nf * 8 + (lane & 3) * 2;
            if (col < CDIM) {
                float v0 = fminf(fmaxf(acc[mf][nf][0] * inv[nf][0], lo), hi) * SF;
                float v1 = fminf(fmaxf(acc[mf][nf][1] * inv[nf][1], lo), hi) * SF;
                float v2 = fminf(fmaxf(acc[mf][nf][2] * inv[nf][0], lo), hi) * SF;
                float v3 = fminf(fmaxf(acc[mf][nf][3] * inv[nf][1], lo), hi) * SF;
                size_t o0 = (size_t)row0 * CDIM + col;
                size_t o1 = (size_t)(row0 + 8) * CDIM + col;
                *(float2*)(out + o0) = make_float2(v0, v1);
                *(float2*)(out + o1) = make_float2(v2, v3);
                *(float2*)(out + (size_t)BQ * CDIM + o0) = make_float2(v0, v1);
                *(float2*)(out + (size_t)BQ * CDIM + o1) = make_float2(v2, v3);
            }
        }
    }
}

// ---------------------------------------------------------------------------
// K5: label-column fixup (merged cos2; fp32-exact)
// ---------------------------------------------------------------------------
__global__ void fixup_kernel(const float* __restrict__ kern,
                             const float* __restrict__ emb,
                             const int*   __restrict__ label,
                             float* __restrict__ out) {
    int b = blockIdx.x, t = threadIdx.x;
    int lab = label[b];
    const float* col0 = kern + lab;                  // t=0 plane
    const float* col1 = kern + (size_t)CDIM + lab;   // t=1 plane
    float dt0 = 0.f, ss0 = 0.f, dt1 = 0.f, ss1 = 0.f;
    for (int e = t; e < EDIM; e += 128) {
        float a = emb[b * EDIM + e];
        float v0 = col0[(size_t)e * TWC];
        float v1 = col1[(size_t)e * TWC];
        dt0 += a * v0; ss0 += v0 * v0;
        dt1 += a * v1; ss1 += v1 * v1;
    }
    __shared__ float s0[128], s1[128], s2[128], s3[128];
    s0[t] = dt0; s1[t] = ss0; s2[t] = dt1; s3[t] = ss1;
    __syncthreads();
    for (int o = 64; o > 0; o >>= 1) {
        if (t < o) { s0[t]+=s0[t+o]; s1[t]+=s1[t+o]; s2[t]+=s2[t+o]; s3[t]+=s3[t+o]; }
        __syncthreads();
    }
    if (t == 0) {
        const float lo = -1.0f + EPSF, hi = 1.0f - EPSF;
        const float thlo = EPSF, thhi = (float)M_PI - EPSF;
        float gang = d_gang[b], gadd = d_gadd[b];
        float w1 = s0[0] * rsqrtf(s1[0]);
        w1 = fminf(fmaxf(w1, lo), hi);
        float th1 = fminf(fmaxf(acosf(w1) + gang, thlo), thhi);
        out[(size_t)b * CDIM + lab] = (cosf(th1) - gadd) * SF;
        float w2 = s2[0] * rsqrtf(s3[0]);
        w2 = fminf(fmaxf(w2, lo), hi);
        float th2 = fminf(fmaxf(acosf(w2) + gang, thlo), thhi);
        out[(size_t)BQ * CDIM + (size_t)b * CDIM + lab] = (cosf(th2) - gadd) * SF;
    }
}

// ---------------------------------------------------------------------------
extern "C" void kernel_launch(void* const* d_in, const int* in_sizes, int n_in,
                              void* d_out, int out_size) {
    const float* emb   = (const float*)d_in[0];  // [512, 512]
    const float* norms = (const float*)d_in[1];  // [512, 1]
    const int*   label = (const int*)  d_in[2];  // [512]
    const float* kern  = (const float*)d_in[3];  // [512, 2, 70722]
    float* out = (float*)d_out;

    cudaFuncSetAttribute(gemm_kernel,
                         cudaFuncAttributeMaxDynamicSharedMemorySize, SMEM_SZ);

    stats_kernel<<<1, BQ>>>(norms, label, out);
    gemm_kernel<<<dim3(4, (CDIM + BN - 1) / BN), 512, SMEM_SZ>>>(emb, kern, out);
    fixup_kernel<<<BQ, 128>>>(kern, emb, label, out);
}

// round 15
// speedup vs baseline: 1.8500x; 1.8500x over previous
#include <cuda_runtime.h>
#include <math.h>
#include <stdint.h>

// Problem constants
#define BQ    512
#define EDIM  512
#define CDIM  70722
#define TWC   (2*CDIM)
#define EPSF  0.001f
#define HF    0.333f
#define SF    64.0f
#define MMARG 0.4f
#define TALPHA 1.0f

// GEMM tile config
#define BM 128
#define BN 128
#define BK 32
#define NCH (EDIM/BK)               // 16 chunks
#define RS 40                       // smem row stride in halves (80B)
#define TILE_H   (BM*RS)
#define TILE_B   (TILE_H*2)         // 10240 bytes per tile
#define BUF_B    (2*TILE_B)         // Ah,Bh = 20480 bytes per stage
#define SSQP_OFF (2*BUF_B)          // 40960
#define SINV_OFF (SSQP_OFF + 512*4) // 43008
#define SMEM_SZ  (SINV_OFF + BN*4)  // 43520

// Scratch
__device__ float d_gang[BQ];
__device__ float d_gadd[BQ];

// ============================ helpers ======================================
__device__ __forceinline__ uint32_t smem_u32(const void* p) {
    uint32_t a;
    asm("{ .reg .u64 t; cvta.to.shared.u64 t, %1; cvt.u32.u64 %0, t; }" : "=r"(a) : "l"(p));
    return a;
}
__device__ __forceinline__ void ldsm4(uint32_t* r, uint32_t addr) {
    asm volatile("ldmatrix.sync.aligned.m8n8.x4.shared.b16 {%0,%1,%2,%3}, [%4];"
        : "=r"(r[0]), "=r"(r[1]), "=r"(r[2]), "=r"(r[3]) : "r"(addr));
}
__device__ __forceinline__ void mma_f16(float* c, const uint32_t* a, const uint32_t* b) {
    asm volatile(
        "mma.sync.aligned.m16n8k16.row.col.f32.f16.f16.f32 "
        "{%0,%1,%2,%3}, {%4,%5,%6,%7}, {%8,%9}, {%0,%1,%2,%3};"
        : "+f"(c[0]), "+f"(c[1]), "+f"(c[2]), "+f"(c[3])
        : "r"(a[0]), "r"(a[1]), "r"(a[2]), "r"(a[3]), "r"(b[0]), "r"(b[1]));
}
__device__ __forceinline__ uint32_t pack_f16(float x0, float x1) {
    uint32_t p;
    asm("cvt.rn.f16x2.f32 %0, %1, %2;" : "=r"(p) : "f"(x1), "f"(x0));
    return p;
}

// ---------------------------------------------------------------------------
// K3: batch statistics + cw_margin output
// ---------------------------------------------------------------------------
__global__ void stats_kernel(const float* __restrict__ norms,
                             const int*   __restrict__ label,
                             float* __restrict__ out) {
    __shared__ float sn[BQ];
    __shared__ int   lab[BQ];
    __shared__ float red[BQ];
    int t = threadIdx.x;
    float x = fminf(fmaxf(norms[t], 0.001f), 100.0f);
    sn[t] = x; lab[t] = label[t]; red[t] = x;
    __syncthreads();
    for (int o = 256; o > 0; o >>= 1) { if (t < o) red[t] += red[t+o]; __syncthreads(); }
    float mean = red[0] * (1.0f / BQ);
    __syncthreads();
    float d = x - mean;
    red[t] = d * d;
    __syncthreads();
    for (int o = 256; o > 0; o >>= 1) { if (t < o) red[t] += red[t+o]; __syncthreads(); }
    float stdv = sqrtf(red[0] / (float)(BQ - 1));
    float batch_mean = mean * TALPHA + (1.0f - TALPHA) * 20.0f;
    float batch_std  = stdv * TALPHA + (1.0f - TALPHA) * 10.0f;
    int ml = lab[t];
    float s = 0.f; int cnt = 0;
    for (int j = 0; j < BQ; ++j) if (lab[j] == ml) { s += sn[j]; cnt++; }
    float cwm = (s / (float)cnt) * TALPHA + (1.0f - TALPHA) * 20.0f;
    float inv = 1.0f / (batch_std + EPSF);
    float ms = fminf(fmaxf((x - batch_mean) * inv * HF, -1.0f), 1.0f);
    d_gang[t] = -MMARG * ms;
    d_gadd[t] =  MMARG + MMARG * ms;
    out[(size_t)2 * BQ * CDIM + t] = fminf(fmaxf((x - cwm) * inv, -1.0f), 1.0f) * HF;
}

// ---------------------------------------------------------------------------
// K4: fp16 mma.sync GEMM, 512 threads, double-buffered.
// Chunk loop unrolled x2: B prefetch at distance 2 with STATIC register sets
// (bpreA / bpreB), A prefetch at distance 1. Two barriers per chunk (R7 shape).
// ---------------------------------------------------------------------------

// One chunk body. CUR is a compile-time 0/1; BPRE is a fixed array name.
#define CHUNK_BODY(CH, CUR, BPRE)                                              \
    do {                                                                       \
        {   /* convert prefetched chunk into buffer CUR */                     \
            uint16_t* Ah = (uint16_t*)(smem + (CUR) * BUF_B);                  \
            uint16_t* Bh = (uint16_t*)(smem + (CUR) * BUF_B + TILE_B);         \
            *(uint2*)&Ah[a_m0 * RS + a_q * 4] =                                \
                make_uint2(pack_f16(apre0.x, apre0.y), pack_f16(apre0.z, apre0.w)); \
            *(uint2*)&Ah[a_m1 * RS + a_q * 4] =                                \
                make_uint2(pack_f16(apre1.x, apre1.y), pack_f16(apre1.z, apre1.w)); \
            _Pragma("unroll")                                                  \
            for (int j = 0; j < 8; j += 2) {                                   \
                float b0 = BPRE[j], b1 = BPRE[j+1];                            \
                ssq += b0 * b0 + b1 * b1;                                      \
                *(uint32_t*)&Bh[bn * RS + bkh + j] = pack_f16(b0, b1);         \
            }                                                                  \
        }                                                                      \
        __syncthreads();                                                       \
        if ((CH) + 1 < NCH) {   /* A for next chunk (distance 1, L2-hot) */    \
            const int kbA = ((CH) + 1) * BK;                                   \
            apre0 = *(const float4*)&A[(size_t)(mbase + a_m0) * EDIM + kbA + a_q * 4]; \
            apre1 = *(const float4*)&A[(size_t)(mbase + a_m1) * EDIM + kbA + a_q * 4]; \
        }                                                                      \
        if ((CH) + 2 < NCH) {   /* B for chunk+2 (distance 2, DRAM) */         \
            const int kbB = ((CH) + 2) * BK;                                   \
            _Pragma("unroll")                                                  \
            for (int j = 0; j < 8; ++j)                                        \
                BPRE[j] = bvalid ? Kn[(size_t)(kbB + bkh + j) * TWC + bc] : 0.f; \
        }                                                                      \
        {   /* math on buffer CUR */                                           \
            const uint32_t aH = sb + (CUR) * BUF_B;                            \
            const uint32_t bH = aH + TILE_B;                                   \
            _Pragma("unroll")                                                  \
            for (int kf = 0; kf < 2; ++kf) {                                   \
                const int kc = kf * 16;                                        \
                uint32_t ah[2][4], bhf[4][2];                                  \
                _Pragma("unroll")                                              \
                for (int mf = 0; mf < 2; ++mf) {                               \
                    uint32_t ad = ((uint32_t)((a_row + mf * 16) * RS + kc + a_coff)) * 2; \
                    ldsm4(ah[mf], aH + ad);                                    \
                }                                                              \
                {                                                              \
                    uint32_t bd0 = ((uint32_t)(b_n * RS + kc + b_koff)) * 2;   \
                    uint32_t bd1 = ((uint32_t)((b_n + 16) * RS + kc + b_koff)) * 2; \
                    uint32_t r[4];                                             \
                    ldsm4(r, bH + bd0);                                        \
                    bhf[0][0]=r[0]; bhf[0][1]=r[1]; bhf[1][0]=r[2]; bhf[1][1]=r[3]; \
                    ldsm4(r, bH + bd1);                                        \
                    bhf[2][0]=r[0]; bhf[2][1]=r[1]; bhf[3][0]=r[2]; bhf[3][1]=r[3]; \
                }                                                              \
                _Pragma("unroll")                                              \
                for (int mf = 0; mf < 2; ++mf)                                 \
                    _Pragma("unroll")                                          \
                    for (int nf = 0; nf < 4; ++nf)                             \
                        mma_f16(acc[mf][nf], ah[mf], bhf[nf]);                 \
            }                                                                  \
        }                                                                      \
        __syncthreads();                                                       \
    } while (0)

__global__ void __launch_bounds__(512, 1)
gemm_kernel(const float* __restrict__ A,       // emb [512,512]
            const float* __restrict__ Kn,      // kernel t=0 plane (stride TWC)
            float* __restrict__ out) {
    extern __shared__ char smem[];
    const uint32_t sb = smem_u32(smem);
    float* ssqp = (float*)(smem + SSQP_OFF);
    float* sinv = (float*)(smem + SINV_OFF);

    const int t = threadIdx.x;
    const int lane = t & 31;
    const int wid = t >> 5;
    const int mbase = blockIdx.x * BM;
    const int cbase = blockIdx.y * BN;
    const int wm = (wid >> 2) * 32;
    const int wn = (wid & 3) * 32;

    float acc[2][4][4];
    #pragma unroll
    for (int i = 0; i < 2; ++i)
        #pragma unroll
        for (int j = 0; j < 4; ++j)
            #pragma unroll
            for (int r = 0; r < 4; ++r) acc[i][j][r] = 0.f;

    // B-load mapping: 4 threads per column, 8 k's each
    const int bn  = t & 127;
    const int bkh = (t >> 7) * 8;
    const int bc  = cbase + bn;
    const bool bvalid = bc < CDIM;
    float ssq = 0.f;

    // A-load mapping: 2 float4 per thread
    const int a_m0 = t >> 3, a_q = t & 7;
    const int a_m1 = a_m0 + 64;

    // ldmatrix lane addressing
    const int a_row  = wm + (lane & 15);
    const int a_coff = (lane >> 4) * 8;
    const int b_n    = wn + ((lane >> 4) << 3) + (lane & 7);
    const int b_koff = ((lane >> 3) & 1) * 8;

    // prefetch registers (all statically named / constant-indexed)
    float4 apre0, apre1;
    float  bpreA[8], bpreB[8];

    // ---- prologue: A(0), B(0) -> set A, B(1) -> set B ----
    apre0 = *(const float4*)&A[(size_t)(mbase + a_m0) * EDIM + a_q * 4];
    apre1 = *(const float4*)&A[(size_t)(mbase + a_m1) * EDIM + a_q * 4];
    #pragma unroll
    for (int j = 0; j < 8; ++j) {
        bpreA[j] = bvalid ? Kn[(size_t)(bkh + j) * TWC + bc] : 0.f;
        bpreB[j] = bvalid ? Kn[(size_t)(BK + bkh + j) * TWC + bc] : 0.f;
    }

    for (int ch = 0; ch < NCH; ch += 2) {
        CHUNK_BODY(ch,     0, bpreA);
        CHUNK_BODY(ch + 1, 1, bpreB);
    }

    // ---- column inverse norms (fp32-exact) ----
    ssqp[t] = ssq;
    __syncthreads();
    if (t < 128)
        sinv[t] = rsqrtf(ssqp[t] + ssqp[t + 128] + ssqp[t + 256] + ssqp[t + 384]);
    __syncthreads();

    // ---- epilogue: clip*scale, dual-plane float2 stores ----
    const float lo = -1.0f + EPSF, hi = 1.0f - EPSF;
    float inv[4][2];
    #pragma unroll
    for (int nf = 0; nf < 4; ++nf) {
        int c0 = wn + nf * 8 + (lane & 3) * 2;
        inv[nf][0] = sinv[c0];
        inv[nf][1] = sinv[c0 + 1];
    }
    #pragma unroll
    for (int mf = 0; mf < 2; ++mf) {
        int row0 = mbase + wm + mf * 16 + (lane >> 2);
        #pragma unroll
        for (int nf = 0; nf < 4; ++nf) {
            int col = cbase + wn + nf * 8 + (lane & 3) * 2;
            if (col < CDIM) {
                float v0 = fminf(fmaxf(acc[mf][nf][0] * inv[nf][0], lo), hi) * SF;
                float v1 = fminf(fmaxf(acc[mf][nf][1] * inv[nf][1], lo), hi) * SF;
                float v2 = fminf(fmaxf(acc[mf][nf][2] * inv[nf][0], lo), hi) * SF;
                float v3 = fminf(fmaxf(acc[mf][nf][3] * inv[nf][1], lo), hi) * SF;
                size_t o0 = (size_t)row0 * CDIM + col;
                size_t o1 = (size_t)(row0 + 8) * CDIM + col;
                *(float2*)(out + o0) = make_float2(v0, v1);
                *(float2*)(out + o1) = make_float2(v2, v3);
                *(float2*)(out + (size_t)BQ * CDIM + o0) = make_float2(v0, v1);
                *(float2*)(out + (size_t)BQ * CDIM + o1) = make_float2(v2, v3);
            }
        }
    }
}

// ---------------------------------------------------------------------------
// K5: label-column fixup (merged cos2; fp32-exact)
// ---------------------------------------------------------------------------
__global__ void fixup_kernel(const float* __restrict__ kern,
                             const float* __restrict__ emb,
                             const int*   __restrict__ label,
                             float* __restrict__ out) {
    int b = blockIdx.x, t = threadIdx.x;
    int lab = label[b];
    const float* col0 = kern + lab;                  // t=0 plane
    const float* col1 = kern + (size_t)CDIM + lab;   // t=1 plane
    float dt0 = 0.f, ss0 = 0.f, dt1 = 0.f, ss1 = 0.f;
    for (int e = t; e < EDIM; e += 128) {
        float a = emb[b * EDIM + e];
        float v0 = col0[(size_t)e * TWC];
        float v1 = col1[(size_t)e * TWC];
        dt0 += a * v0; ss0 += v0 * v0;
        dt1 += a * v1; ss1 += v1 * v1;
    }
    __shared__ float s0[128], s1[128], s2[128], s3[128];
    s0[t] = dt0; s1[t] = ss0; s2[t] = dt1; s3[t] = ss1;
    __syncthreads();
    for (int o = 64; o > 0; o >>= 1) {
        if (t < o) { s0[t]+=s0[t+o]; s1[t]+=s1[t+o]; s2[t]+=s2[t+o]; s3[t]+=s3[t+o]; }
        __syncthreads();
    }
    if (t == 0) {
        const float lo = -1.0f + EPSF, hi = 1.0f - EPSF;
        const float thlo = EPSF, thhi = (float)M_PI - EPSF;
        float gang = d_gang[b], gadd = d_gadd[b];
        float w1 = s0[0] * rsqrtf(s1[0]);
        w1 = fminf(fmaxf(w1, lo), hi);
        float th1 = fminf(fmaxf(acosf(w1) + gang, thlo), thhi);
        out[(size_t)b * CDIM + lab] = (cosf(th1) - gadd) * SF;
        float w2 = s2[0] * rsqrtf(s3[0]);
        w2 = fminf(fmaxf(w2, lo), hi);
        float th2 = fminf(fmaxf(acosf(w2) + gang, thlo), thhi);
        out[(size_t)BQ * CDIM + (size_t)b * CDIM + lab] = (cosf(th2) - gadd) * SF;
    }
}

// ---------------------------------------------------------------------------
extern "C" void kernel_launch(void* const* d_in, const int* in_sizes, int n_in,
                              void* d_out, int out_size) {
    const float* emb   = (const float*)d_in[0];  // [512, 512]
    const float* norms = (const float*)d_in[1];  // [512, 1]
    const int*   label = (const int*)  d_in[2];  // [512]
    const float* kern  = (const float*)d_in[3];  // [512, 2, 70722]
    float* out = (float*)d_out;

    cudaFuncSetAttribute(gemm_kernel,
                         cudaFuncAttributeMaxDynamicSharedMemorySize, SMEM_SZ);

    stats_kernel<<<1, BQ>>>(norms, label, out);
    gemm_kernel<<<dim3(4, (CDIM + BN - 1) / BN), 512, SMEM_SZ>>>(emb, kern, out);
    fixup_kernel<<<BQ, 128>>>(kern, emb, label, out);
}

// round 17
// speedup vs baseline: 2.0942x; 1.1320x over previous
#include <cuda_runtime.h>
#include <math.h>
#include <stdint.h>

// Problem constants
#define BQ    512
#define EDIM  512
#define CDIM  70722
#define CPAD  70784                 // 553*128
#define TWC   (2*CDIM)
#define EPSF  0.001f
#define HF    0.333f
#define SF    64.0f
#define MMARG 0.4f
#define TALPHA 1.0f

// GEMM tile config
#define BM 128
#define BN 128
#define BK 32
#define NCH (EDIM/BK)               // 16 chunks
#define RS 40                       // smem row stride in halves (80B)
#define TILE_B   (BM*RS*2)          // 10240 bytes per (A or B) tile
#define STAGE_B  (2*TILE_B)         // 20480 per stage
#define NSTAGE   4
#define SINV_OFF (NSTAGE*STAGE_B)   // 81920
#define SMEM_SZ  (SINV_OFF + BN*4)  // 82432

// Scratch (static __device__ arrays — the sanctioned no-alloc mechanism)
__device__ uint16_t d_B16[(size_t)CPAD * EDIM];   // fp16 kernel t=0, TRANSPOSED [c][e]
__device__ uint16_t d_A16[BQ * EDIM];             // fp16 embeddings [m][e]
__device__ float    d_invn0[CPAD];
__device__ float    d_gang[BQ];
__device__ float    d_gadd[BQ];

// ============================ helpers ======================================
__device__ __forceinline__ uint32_t smem_u32(const void* p) {
    uint32_t a;
    asm("{ .reg .u64 t; cvta.to.shared.u64 t, %1; cvt.u32.u64 %0, t; }" : "=r"(a) : "l"(p));
    return a;
}
__device__ __forceinline__ void ldsm4(uint32_t* r, uint32_t addr) {
    asm volatile("ldmatrix.sync.aligned.m8n8.x4.shared.b16 {%0,%1,%2,%3}, [%4];"
        : "=r"(r[0]), "=r"(r[1]), "=r"(r[2]), "=r"(r[3]) : "r"(addr));
}
__device__ __forceinline__ void mma_f16(float* c, const uint32_t* a, const uint32_t* b) {
    asm volatile(
        "mma.sync.aligned.m16n8k16.row.col.f32.f16.f16.f32 "
        "{%0,%1,%2,%3}, {%4,%5,%6,%7}, {%8,%9}, {%0,%1,%2,%3};"
        : "+f"(c[0]), "+f"(c[1]), "+f"(c[2]), "+f"(c[3])
        : "r"(a[0]), "r"(a[1]), "r"(a[2]), "r"(a[3]), "r"(b[0]), "r"(b[1]));
}
__device__ __forceinline__ uint32_t pack_f16(float x0, float x1) {
    uint32_t p;
    asm("cvt.rn.f16x2.f32 %0, %1, %2;" : "=r"(p) : "f"(x1), "f"(x0));
    return p;
}
__device__ __forceinline__ void cp_async16(uint32_t dst, const void* src) {
    asm volatile("cp.async.cg.shared.global [%0], [%1], 16;"
        :: "r"(dst), "l"(src) : "memory");
}
#define CP_COMMIT() asm volatile("cp.async.commit_group;" ::: "memory")
#define CP_WAIT2()  asm volatile("cp.async.wait_group 2;"  ::: "memory")

// ---------------------------------------------------------------------------
// K0: convert kernel t=0 plane -> fp16 transposed [c][e], fused column norms.
// 553 blocks x 512 threads; block owns 128 columns.
// FIX vs R15: output copy is uint4 (16B = 8 halves), matching the 8-half span
// each thread owns. (R15 used uint2 and left half of d_B16 unwritten.)
// ---------------------------------------------------------------------------
__global__ void convB_kernel(const float* __restrict__ Kn) {
    __shared__ uint16_t tile[128 * RS];
    __shared__ float ssqs[512];
    const int t = threadIdx.x;
    const int cl = t & 127;
    const int esub = t >> 7;            // 0..3
    const size_t c = (size_t)blockIdx.x * 128 + cl;
    const int n = t >> 2, kq = (t & 3) * 8;
    float ssq = 0.f;

    for (int e0 = 0; e0 < EDIM; e0 += 32) {
        float v[8];
        #pragma unroll
        for (int i = 0; i < 8; ++i) {
            int e = e0 + esub * 8 + i;
            v[i] = Kn[(size_t)e * TWC + c];   // coalesced: consecutive c per fixed e
            ssq += v[i] * v[i];
        }
        #pragma unroll
        for (int i = 0; i < 8; i += 2)
            *(uint32_t*)&tile[cl * RS + esub * 8 + i] = pack_f16(v[i], v[i+1]);
        __syncthreads();
        // 16B per thread out: column (bid*128+n), e range [e0+kq, e0+kq+8)
        uint4 val = *(uint4*)&tile[n * RS + kq];
        *(uint4*)&d_B16[((size_t)blockIdx.x * 128 + n) * EDIM + e0 + kq] = val;
        __syncthreads();
    }
    ssqs[t] = ssq;
    __syncthreads();
    if (t < 128) {
        size_t cc = (size_t)blockIdx.x * 128 + t;
        d_invn0[cc] = rsqrtf(ssqs[t] + ssqs[t+128] + ssqs[t+256] + ssqs[t+384]);
    }
}

// ---------------------------------------------------------------------------
// K1: convert embeddings -> fp16 (same layout). 128 blocks x 512 threads.
// ---------------------------------------------------------------------------
__global__ void convA_kernel(const float* __restrict__ A) {
    int idx = blockIdx.x * 512 + threadIdx.x;     // float4 index, 65536 total
    float4 v = ((const float4*)A)[idx];
    ((uint2*)d_A16)[idx] = make_uint2(pack_f16(v.x, v.y), pack_f16(v.z, v.w));
}

// ---------------------------------------------------------------------------
// K3: batch statistics + cw_margin output
// ---------------------------------------------------------------------------
__global__ void stats_kernel(const float* __restrict__ norms,
                             const int*   __restrict__ label,
                             float* __restrict__ out) {
    __shared__ float sn[BQ];
    __shared__ int   lab[BQ];
    __shared__ float red[BQ];
    int t = threadIdx.x;
    float x = fminf(fmaxf(norms[t], 0.001f), 100.0f);
    sn[t] = x; lab[t] = label[t]; red[t] = x;
    __syncthreads();
    for (int o = 256; o > 0; o >>= 1) { if (t < o) red[t] += red[t+o]; __syncthreads(); }
    float mean = red[0] * (1.0f / BQ);
    __syncthreads();
    float d = x - mean;
    red[t] = d * d;
    __syncthreads();
    for (int o = 256; o > 0; o >>= 1) { if (t < o) red[t] += red[t+o]; __syncthreads(); }
    float stdv = sqrtf(red[0] / (float)(BQ - 1));
    float batch_mean = mean * TALPHA + (1.0f - TALPHA) * 20.0f;
    float batch_std  = stdv * TALPHA + (1.0f - TALPHA) * 10.0f;
    int ml = lab[t];
    float s = 0.f; int cnt = 0;
    for (int j = 0; j < BQ; ++j) if (lab[j] == ml) { s += sn[j]; cnt++; }
    float cwm = (s / (float)cnt) * TALPHA + (1.0f - TALPHA) * 20.0f;
    float inv = 1.0f / (batch_std + EPSF);
    float ms = fminf(fmaxf((x - batch_mean) * inv * HF, -1.0f), 1.0f);
    d_gang[t] = -MMARG * ms;
    d_gadd[t] =  MMARG + MMARG * ms;
    out[(size_t)2 * BQ * CDIM + t] = fminf(fmaxf((x - cwm) * inv, -1.0f), 1.0f) * HF;
}

// ---------------------------------------------------------------------------
// K4: fp16 mma.sync GEMM from pre-converted fp16 operands.
// 4-stage cp.async ring, ONE barrier per chunk. 512 thr, 16 warps (4m x 4n).
// ---------------------------------------------------------------------------
__global__ void __launch_bounds__(512, 1)
gemm_kernel(float* __restrict__ out) {
    extern __shared__ char smem[];
    const uint32_t sb = smem_u32(smem);
    float* sinv = (float*)(smem + SINV_OFF);

    const int t = threadIdx.x;
    const int lane = t & 31;
    const int wid = t >> 5;
    const int mbase = blockIdx.x * BM;
    const int cbase = blockIdx.y * BN;
    const int wm = (wid >> 2) * 32;
    const int wn = (wid & 3) * 32;

    // cp.async mapping: one 16B A copy + one 16B B copy per thread per stage
    const int cm = t >> 2, ckq = (t & 3) * 8;   // row 0..127, k-offset 0/8/16/24
    const uint16_t* asrc0 = d_A16 + (size_t)(mbase + cm) * EDIM + ckq;
    const uint16_t* bsrc0 = d_B16 + (size_t)(cbase + cm) * EDIM + ckq;
    const uint32_t adst0 = sb + (cm * RS + ckq) * 2;
    const uint32_t bdst0 = adst0 + TILE_B;

    // epilogue inverse norms -> smem (overlaps with pipeline fill;
    // first mainloop __syncthreads orders it before epilogue reads)
    if (t < 128) {
        int c = cbase + t;
        sinv[t] = (c < CDIM) ? d_invn0[c] : 1.0f;
    }

    float acc[2][4][4];
    #pragma unroll
    for (int i = 0; i < 2; ++i)
        #pragma unroll
        for (int j = 0; j < 4; ++j)
            #pragma unroll
            for (int r = 0; r < 4; ++r) acc[i][j][r] = 0.f;

    // ldmatrix lane addressing
    const int a_row  = wm + (lane & 15);
    const int a_coff = (lane >> 4) * 8;
    const int b_n    = wn + ((lane >> 4) << 3) + (lane & 7);
    const int b_koff = ((lane >> 3) & 1) * 8;

    // ---- prologue: fill stages 0..2 ----
    #pragma unroll
    for (int s = 0; s < 3; ++s) {
        cp_async16(adst0 + s * STAGE_B, asrc0 + s * BK);
        cp_async16(bdst0 + s * STAGE_B, bsrc0 + s * BK);
        CP_COMMIT();
    }

    #pragma unroll
    for (int ch = 0; ch < NCH; ++ch) {
        const int stage = ch & (NSTAGE - 1);
        CP_WAIT2();
        __syncthreads();

        // issue loads for chunk ch+3 into the stage consumed at ch-1
        if (ch + 3 < NCH) {
            const int ns = (ch + 3) & (NSTAGE - 1);
            cp_async16(adst0 + ns * STAGE_B, asrc0 + (ch + 3) * BK);
            cp_async16(bdst0 + ns * STAGE_B, bsrc0 + (ch + 3) * BK);
        }
        CP_COMMIT();   // always commit (keeps wait_group accounting uniform)

        // ---- math on current stage ----
        const uint32_t aH = sb + stage * STAGE_B;
        const uint32_t bH = aH + TILE_B;
        #pragma unroll
        for (int kf = 0; kf < 2; ++kf) {
            const int kc = kf * 16;
            uint32_t ah[2][4], bhf[4][2];
            #pragma unroll
            for (int mf = 0; mf < 2; ++mf) {
                uint32_t ad = ((uint32_t)((a_row + mf * 16) * RS + kc + a_coff)) * 2;
                ldsm4(ah[mf], aH + ad);
            }
            {
                uint32_t bd0 = ((uint32_t)(b_n * RS + kc + b_koff)) * 2;
                uint32_t bd1 = ((uint32_t)((b_n + 16) * RS + kc + b_koff)) * 2;
                uint32_t r[4];
                ldsm4(r, bH + bd0);
                bhf[0][0]=r[0]; bhf[0][1]=r[1]; bhf[1][0]=r[2]; bhf[1][1]=r[3];
                ldsm4(r, bH + bd1);
                bhf[2][0]=r[0]; bhf[2][1]=r[1]; bhf[3][0]=r[2]; bhf[3][1]=r[3];
            }
            #pragma unroll
            for (int mf = 0; mf < 2; ++mf)
                #pragma unroll
                for (int nf = 0; nf < 4; ++nf)
                    mma_f16(acc[mf][nf], ah[mf], bhf[nf]);
        }
        // no tail barrier: stage reused only after the sync in iteration ch+1
    }

    // ---- epilogue: clip*scale, dual-plane float2 stores ----
    const float lo = -1.0f + EPSF, hi = 1.0f - EPSF;
    float inv[4][2];
    #pragma unroll
    for (int nf = 0; nf < 4; ++nf) {
        int c0 = wn + nf * 8 + (lane & 3) * 2;
        inv[nf][0] = sinv[c0];
        inv[nf][1] = sinv[c0 + 1];
    }
    #pragma unroll
    for (int mf = 0; mf < 2; ++mf) {
        int row0 = mbase + wm + mf * 16 + (lane >> 2);
        #pragma unroll
        for (int nf = 0; nf < 4; ++nf) {
            int col = cbase + wn + nf * 8 + (lane & 3) * 2;
            if (col < CDIM) {
                float v0 = fminf(fmaxf(acc[mf][nf][0] * inv[nf][0], lo), hi) * SF;
                float v1 = fminf(fmaxf(acc[mf][nf][1] * inv[nf][1], lo), hi) * SF;
                float v2 = fminf(fmaxf(acc[mf][nf][2] * inv[nf][0], lo), hi) * SF;
                float v3 = fminf(fmaxf(acc[mf][nf][3] * inv[nf][1], lo), hi) * SF;
                size_t o0 = (size_t)row0 * CDIM + col;
                size_t o1 = (size_t)(row0 + 8) * CDIM + col;
                *(float2*)(out + o0) = make_float2(v0, v1);
                *(float2*)(out + o1) = make_float2(v2, v3);
                *(float2*)(out + (size_t)BQ * CDIM + o0) = make_float2(v0, v1);
                *(float2*)(out + (size_t)BQ * CDIM + o1) = make_float2(v2, v3);
            }
        }
    }
}

// ---------------------------------------------------------------------------
// K5: label-column fixup (merged cos2; fp32-exact)
// ---------------------------------------------------------------------------
__global__ void fixup_kernel(const float* __restrict__ kern,
                             const float* __restrict__ emb,
                             const int*   __restrict__ label,
                             float* __restrict__ out) {
    int b = blockIdx.x, t = threadIdx.x;
    int lab = label[b];
    const float* col0 = kern + lab;                  // t=0 plane
    const float* col1 = kern + (size_t)CDIM + lab;   // t=1 plane
    float dt0 = 0.f, ss0 = 0.f, dt1 = 0.f, ss1 = 0.f;
    for (int e = t; e < EDIM; e += 128) {
        float a = emb[b * EDIM + e];
        float v0 = col0[(size_t)e * TWC];
        float v1 = col1[(size_t)e * TWC];
        dt0 += a * v0; ss0 += v0 * v0;
        dt1 += a * v1; ss1 += v1 * v1;
    }
    __shared__ float s0[128], s1[128], s2[128], s3[128];
    s0[t] = dt0; s1[t] = ss0; s2[t] = dt1; s3[t] = ss1;
    __syncthreads();
    for (int o = 64; o > 0; o >>= 1) {
        if (t < o) { s0[t]+=s0[t+o]; s1[t]+=s1[t+o]; s2[t]+=s2[t+o]; s3[t]+=s3[t+o]; }
        __syncthreads();
    }
    if (t == 0) {
        const float lo = -1.0f + EPSF, hi = 1.0f - EPSF;
        const float thlo = EPSF, thhi = (float)M_PI - EPSF;
        float gang = d_gang[b], gadd = d_gadd[b];
        float w1 = s0[0] * rsqrtf(s1[0]);
        w1 = fminf(fmaxf(w1, lo), hi);
        float th1 = fminf(fmaxf(acosf(w1) + gang, thlo), thhi);
        out[(size_t)b * CDIM + lab] = (cosf(th1) - gadd) * SF;
        float w2 = s2[0] * rsqrtf(s3[0]);
        w2 = fminf(fmaxf(w2, lo), hi);
        float th2 = fminf(fmaxf(acosf(w2) + gang, thlo), thhi);
        out[(size_t)BQ * CDIM + (size_t)b * CDIM + lab] = (cosf(th2) - gadd) * SF;
    }
}

// ---------------------------------------------------------------------------
extern "C" void kernel_launch(void* const* d_in, const int* in_sizes, int n_in,
                              void* d_out, int out_size) {
    const float* emb   = (const float*)d_in[0];  // [512, 512]
    const float* norms = (const float*)d_in[1];  // [512, 1]
    const int*   label = (const int*)  d_in[2];  // [512]
    const float* kern  = (const float*)d_in[3];  // [512, 2, 70722]
    float* out = (float*)d_out;

    cudaFuncSetAttribute(gemm_kernel,
                         cudaFuncAttributeMaxDynamicSharedMemorySize, SMEM_SZ);

    convB_kernel<<<CPAD / 128, 512>>>(kern);
    convA_kernel<<<128, 512>>>(emb);
    stats_kernel<<<1, BQ>>>(norms, label, out);
    gemm_kernel<<<dim3(4, CPAD / BN), 512, SMEM_SZ>>>(out);
    fixup_kernel<<<BQ, 128>>>(kern, emb, label, out);
}